// round 16
// baseline (speedup 1.0000x reference)
#include <cuda_runtime.h>

// ---------------------------------------------------------------------------
// EGNN edge/node block, round 15.
// Base R13 (224.0us best) + GEMM1 K 24->16: the radial column is folded into
// epilogue-1 as a rank-1 FMA (radial[e] * W1row128[c]), removing the 7
// zero-pad K columns and one full k-step of GEMM1. Persistent p_kernel,
// 1024-thr node kernel unchanged.
// N=50000, E=800000, D=64, H=64, EF=16.
// ---------------------------------------------------------------------------

#define NN      50000
#define DD      64
#define HH      64
#define E_TILE  128
#define WSTR    72     // weight row stride (72%32=8, conflict-free)
#define PSTR    68     // buf row stride (68%32=4); 272B row, 16B-aligned
#define FSSTR   20     // fsmall row stride (20%32=20, conflict-free; 80B rows)
#define K1S     16     // K of edge layer 1 (2 k-steps, edge_feat only)

__device__ float g_hneigh[NN * HH];
__device__ float g_P[NN * 128];   // [n][0:64]=h@W1_src, [64:128]=h@W1_dst

__device__ __forceinline__ float silu(float x) {
    return x / (1.0f + __expf(-x));
}
__device__ __forceinline__ unsigned f2tf(float x) {
    unsigned r;
    asm("cvt.rna.tf32.f32 %0, %1;" : "=r"(r) : "f"(x));
    return r;
}
__device__ __forceinline__ void mma_tf32(float d[4], const unsigned a[4],
                                         const unsigned b[2]) {
    asm volatile(
        "mma.sync.aligned.m16n8k8.row.col.f32.tf32.tf32.f32 "
        "{%0,%1,%2,%3}, {%4,%5,%6,%7}, {%8,%9}, {%0,%1,%2,%3};"
        : "+f"(d[0]), "+f"(d[1]), "+f"(d[2]), "+f"(d[3])
        : "r"(a[0]), "r"(a[1]), "r"(a[2]), "r"(a[3]), "r"(b[0]), "r"(b[1]));
}
__device__ __forceinline__ void cp16(unsigned saddr, const void* g) {
    asm volatile("cp.async.ca.shared.global [%0], [%1], 16;"
                 :: "r"(saddr), "l"(g));
}
__device__ __forceinline__ void bulk_red_add(float* gptr, unsigned saddr,
                                             int bytes) {
    unsigned long long g;
    asm("cvta.to.global.u64 %0, %1;" : "=l"(g) : "l"(gptr));
    asm volatile(
        "cp.reduce.async.bulk.global.shared::cta.bulk_group.add.f32 "
        "[%0], [%1], %2;"
        :: "l"(g), "r"(saddr), "r"(bytes) : "memory");
}
__device__ __forceinline__ void bar_pair(int id) {
    asm volatile("bar.sync %0, 64;" :: "r"(id) : "memory");
}

// ---------------------------------------------------------------------------
// P kernel: persistent single wave (2 CTAs/SM). P tiles + fused zeroing.
// ---------------------------------------------------------------------------
#define ASTR  68
#define BSTR2 136

__global__ void __launch_bounds__(512, 2)
p_kernel(const float* __restrict__ node_feat,
         const float* __restrict__ We1,
         int N, int pTiles)
{
    const int tid = threadIdx.x;

    extern __shared__ float sm[];
    float* As = sm;                 // 128*68
    float* Bs = As + 128 * ASTR;    // 64*136

    for (int i = tid; i < 64 * 128; i += 512) {
        int k = i >> 7, j = i & 127;
        float v = (j < 64) ? We1[k * HH + j] : We1[(64 + k) * HH + (j - 64)];
        Bs[k * BSTR2 + j] = __uint_as_float(f2tf(v));
    }

    const int warp = tid >> 5, lane = tid & 31;
    const int gid = lane >> 2, tig = lane & 3;
    const int mrow  = (warp & 3) * 32;
    const int nbase = (warp >> 2) * 32;
    const float4* nf4 = (const float4*)node_feat;
    const unsigned* bu = (const unsigned*)Bs;

    for (int t = blockIdx.x; t < pTiles; t += gridDim.x) {
        const int base = t * 128;
        __syncthreads();

        for (int idx = tid; idx < 128 * 16; idx += 512) {
            int r = idx >> 4, c = idx & 15;
            int n = base + r;
            if (n >= N) n = N - 1;
            ((float4*)(As + r * ASTR))[c] = nf4[(long)n * 16 + c];
        }
        __syncthreads();

        float d[2][4][4];
        #pragma unroll
        for (int mi = 0; mi < 2; mi++)
            #pragma unroll
            for (int nj = 0; nj < 4; nj++)
                #pragma unroll
                for (int q = 0; q < 4; q++) d[mi][nj][q] = 0.0f;

        #pragma unroll
        for (int ks = 0; ks < 8; ks++) {
            const int kk = ks * 8;
            unsigned a[2][4];
            #pragma unroll
            for (int mi = 0; mi < 2; mi++) {
                int r0 = mrow + mi * 16 + gid;
                const float* fp  = As + r0 * ASTR + kk + tig;
                const float* fp8 = fp + 8 * ASTR;
                a[mi][0] = f2tf(fp[0]);
                a[mi][1] = f2tf(fp8[0]);
                a[mi][2] = f2tf(fp[4]);
                a[mi][3] = f2tf(fp8[4]);
            }
            #pragma unroll
            for (int nj = 0; nj < 4; nj++) {
                int n = nbase + nj * 8 + gid;
                unsigned bb[2];
                bb[0] = bu[(kk + tig) * BSTR2 + n];
                bb[1] = bu[(kk + tig + 4) * BSTR2 + n];
                mma_tf32(d[0][nj], a[0], bb);
                mma_tf32(d[1][nj], a[1], bb);
            }
        }
        #pragma unroll
        for (int mi = 0; mi < 2; mi++) {
            int r0 = mrow + mi * 16 + gid;
            #pragma unroll
            for (int nj = 0; nj < 4; nj++) {
                int c0 = nbase + nj * 8 + tig * 2;
                int n0 = base + r0, n1 = base + r0 + 8;
                if (n0 < N)
                    *(float2*)(g_P + (long)n0 * 128 + c0)
                        = make_float2(d[mi][nj][0], d[mi][nj][1]);
                if (n1 < N)
                    *(float2*)(g_P + (long)n1 * 128 + c0)
                        = make_float2(d[mi][nj][2], d[mi][nj][3]);
            }
        }
    }

    {
        float4* h4 = (float4*)g_hneigh;
        const int total4 = NN * HH / 4;
        for (int i = blockIdx.x * 512 + tid; i < total4; i += gridDim.x * 512)
            h4[i] = make_float4(0.f, 0.f, 0.f, 0.f);
    }
}

// ---------------------------------------------------------------------------
// Edge kernel. E_TILE=128, 256 thr, 3 CTAs/SM. GEMM1 K=16 (edge_feat only);
// radial folded into epilogue-1 as rank-1 FMA. R13 sync structure.
// ---------------------------------------------------------------------------
#define ETHREADS 256

__global__ void __launch_bounds__(ETHREADS, 3)
edge_kernel(const float* __restrict__ coord,
            const float* __restrict__ edge_feat,
            const int*   __restrict__ src,
            const int*   __restrict__ dst,
            const float* __restrict__ We1,
            const float* __restrict__ be1,
            const float* __restrict__ We2,
            const float* __restrict__ be2,
            int E)
{
    extern __shared__ float sm[];
    float* W1s    = sm;                      // 16*72 = 1152
    float* W2s    = W1s + K1S * WSTR;        // 64*72 = 4608
    float* b1s    = W2s + HH * WSTR;         // 64
    float* b2s    = b1s + HH;                // 64
    float* w128s  = b2s + HH;                // 64 (radial weight row, fp32)
    float* rs     = w128s + HH;              // 128 (radial per edge)
    int*   ds     = (int*)(rs + E_TILE);     // 128
    float* buf    = (float*)(ds + E_TILE);   // 128*68 (presum/m/msg)
    float* fsmall = buf + E_TILE * PSTR;     // 128*20
    // total 17472 floats = 69888 B -> 3 CTAs/SM; buf at 24832B (16B-aligned)

    const int tid = threadIdx.x;

    // W1small rows 0-15 = edge_feat rows (orig 129-144)
    for (int i = tid; i < K1S * HH; i += ETHREADS) {
        int r = i / HH, c = i % HH;
        W1s[r * WSTR + c] = __uint_as_float(f2tf(We1[(129 + r) * HH + c]));
    }
    for (int i = tid; i < HH * HH; i += ETHREADS) {
        int r = i / HH, c = i % HH;
        W2s[r * WSTR + c] = __uint_as_float(f2tf(We2[i]));
    }
    if (tid < HH) {
        b1s[tid]   = be1[tid];
        b2s[tid]   = be2[tid];
        w128s[tid] = __uint_as_float(f2tf(We1[128 * HH + tid]));
    }

    const int warp = tid >> 5;
    const int lane = tid & 31;
    const int gid  = lane >> 2;
    const int tig  = lane & 3;
    const int mrow  = (warp & 3) * 32;
    const int nbase = (warp >> 2) * 32;
    const int pairb = 1 + (warp & 3);       // named barrier id for row-group
    const int half  = lane >> 4;            // 0/1
    const int j     = lane & 15;            // 0..15

    const float4* P4 = (const float4*)g_P;
    const unsigned fsb = (unsigned)__cvta_generic_to_shared(fsmall);
    const unsigned msb = (unsigned)__cvta_generic_to_shared(buf);

    __syncthreads();

    const int nTiles = (E + E_TILE - 1) / E_TILE;
    for (int t = blockIdx.x; t < nTiles; t += gridDim.x) {
        const int base = t * E_TILE;

        // ========== STAGE A: no writes to buf/ds/rs ==========
        const int eb = base + warp * 16;
        int egi = eb + j; if (egi >= E) egi = E - 1;
        const int myidx = (lane < 16) ? src[egi] : dst[egi];

        #pragma unroll
        for (int r = 0; r < 2; r++) {
            int el = warp * 16 + r * 8 + (lane >> 2);
            int eg = base + el; if (eg >= E) eg = E - 1;
            int c = lane & 3;
            cp16(fsb + el * (FSSTR * 4) + c * 16,
                 edge_feat + (long)eg * 16 + c * 4);
        }
        asm volatile("cp.async.commit_group;");

        // radial (lanes 0..15 compute; stored after the drain) + dst idx
        int s_r = __shfl_sync(0xffffffffu, myidx, j);
        int d_r = __shfl_sync(0xffffffffu, myidx, 16 + j);
        float rad = 0.0f;
        if (lane < 16) {
            float cx = coord[s_r * 3 + 0] - coord[d_r * 3 + 0];
            float cy = coord[s_r * 3 + 1] - coord[d_r * 3 + 1];
            float cz = coord[s_r * 3 + 2] - coord[d_r * 3 + 2];
            rad = cx * cx + cy * cy + cz * cz;
        }

        // chunk-1 P gather BEFORE bulk drain
        float4 ps1[4], pd1[4];
        #pragma unroll
        for (int i = 0; i < 4; i++) {
            int el = i * 2 + half;
            int s = __shfl_sync(0xffffffffu, myidx, el);
            int d = __shfl_sync(0xffffffffu, myidx, 16 + el);
            ps1[i] = P4[(long)s * 32 + j];
            pd1[i] = P4[(long)d * 32 + 16 + j];
        }

        // ========== drain previous tile's bulk scatter ==========
        asm volatile("cp.async.bulk.wait_group 0;" ::: "memory");
        __syncthreads();

        if (lane < 16) rs[warp * 16 + j] = rad;

        // chunk-1 store + chunk-2 load/store
        #pragma unroll
        for (int i = 0; i < 4; i++) {
            int el = warp * 16 + i * 2 + half;
            float4 v = make_float4(ps1[i].x + pd1[i].x, ps1[i].y + pd1[i].y,
                                   ps1[i].z + pd1[i].z, ps1[i].w + pd1[i].w);
            *(float4*)(buf + el * PSTR + j * 4) = v;
        }
        {
            float4 ps2[4], pd2[4];
            #pragma unroll
            for (int i = 0; i < 4; i++) {
                int el = (4 + i) * 2 + half;
                int s = __shfl_sync(0xffffffffu, myidx, el);
                int d = __shfl_sync(0xffffffffu, myidx, 16 + el);
                ps2[i] = P4[(long)s * 32 + j];
                pd2[i] = P4[(long)d * 32 + 16 + j];
            }
            #pragma unroll
            for (int i = 0; i < 4; i++) {
                int el = warp * 16 + (4 + i) * 2 + half;
                float4 v = make_float4(ps2[i].x + pd2[i].x, ps2[i].y + pd2[i].y,
                                       ps2[i].z + pd2[i].z, ps2[i].w + pd2[i].w);
                *(float4*)(buf + el * PSTR + j * 4) = v;
            }
        }
        if (lane >= 16) ds[warp * 16 + j] = d_r;

        asm volatile("cp.async.wait_group 0;");
        __syncthreads();

        // ========== GEMM1: [128,16]@[16,64] (2 ksteps) ==========
        float d1[2][4][4];
        #pragma unroll
        for (int mi = 0; mi < 2; mi++)
            #pragma unroll
            for (int nj = 0; nj < 4; nj++)
                #pragma unroll
                for (int q = 0; q < 4; q++) d1[mi][nj][q] = 0.0f;

        const unsigned* w1u = (const unsigned*)W1s;
        #pragma unroll
        for (int ks = 0; ks < 2; ks++) {
            const int kk = ks * 8;
            unsigned a[2][4];
            #pragma unroll
            for (int mi = 0; mi < 2; mi++) {
                int r0 = mrow + mi * 16 + gid;
                const float* fp  = fsmall + r0 * FSSTR + kk + tig;
                const float* fp8 = fp + 8 * FSSTR;
                a[mi][0] = f2tf(fp[0]);
                a[mi][1] = f2tf(fp8[0]);
                a[mi][2] = f2tf(fp[4]);
                a[mi][3] = f2tf(fp8[4]);
            }
            #pragma unroll
            for (int nj = 0; nj < 4; nj++) {
                int n = nbase + nj * 8 + gid;
                unsigned bb[2];
                bb[0] = w1u[(kk + tig) * WSTR + n];
                bb[1] = w1u[(kk + tig + 4) * WSTR + n];
                mma_tf32(d1[0][nj], a[0], bb);
                mma_tf32(d1[1][nj], a[1], bb);
            }
        }

        // ---- epilogue1 IN-PLACE: m = tf32(silu(d1 + presum
        //      + radial*w128 + b1)) ----
        #pragma unroll
        for (int mi = 0; mi < 2; mi++) {
            int r0 = mrow + mi * 16 + gid;
            float rad0 = rs[r0], rad1 = rs[r0 + 8];
            #pragma unroll
            for (int nj = 0; nj < 4; nj++) {
                int c0 = nbase + nj * 8 + tig * 2;
                float bb0 = b1s[c0], bb1 = b1s[c0 + 1];
                float w0 = w128s[c0], w1 = w128s[c0 + 1];
                float* p00 = buf + r0 * PSTR + c0;
                float* p10 = buf + (r0 + 8) * PSTR + c0;
                p00[0] = __uint_as_float(f2tf(
                    silu(d1[mi][nj][0] + p00[0] + rad0 * w0 + bb0)));
                p00[1] = __uint_as_float(f2tf(
                    silu(d1[mi][nj][1] + p00[1] + rad0 * w1 + bb1)));
                p10[0] = __uint_as_float(f2tf(
                    silu(d1[mi][nj][2] + p10[0] + rad1 * w0 + bb0)));
                p10[1] = __uint_as_float(f2tf(
                    silu(d1[mi][nj][3] + p10[1] + rad1 * w1 + bb1)));
            }
        }
        bar_pair(pairb);   // col-group partner must see m complete

        // ========== GEMM2: [128,64]@[64,64] ==========
        float d2[2][4][4];
        #pragma unroll
        for (int mi = 0; mi < 2; mi++)
            #pragma unroll
            for (int nj = 0; nj < 4; nj++)
                #pragma unroll
                for (int q = 0; q < 4; q++) d2[mi][nj][q] = 0.0f;

        const unsigned* msu = (const unsigned*)buf;
        const unsigned* w2u = (const unsigned*)W2s;
        #pragma unroll
        for (int ks = 0; ks < 8; ks++) {
            const int kk = ks * 8;
            unsigned a[2][4];
            #pragma unroll
            for (int mi = 0; mi < 2; mi++) {
                int r0 = mrow + mi * 16 + gid;
                const unsigned* mp  = msu + r0 * PSTR + kk + tig;
                const unsigned* mp8 = mp + 8 * PSTR;
                a[mi][0] = mp[0];
                a[mi][1] = mp8[0];
                a[mi][2] = mp[4];
                a[mi][3] = mp8[4];
            }
            #pragma unroll
            for (int nj = 0; nj < 4; nj++) {
                int n = nbase + nj * 8 + gid;
                unsigned bb[2];
                bb[0] = w2u[(kk + tig) * WSTR + n];
                bb[1] = w2u[(kk + tig + 4) * WSTR + n];
                mma_tf32(d2[0][nj], a[0], bb);
                mma_tf32(d2[1][nj], a[1], bb);
            }
        }
        bar_pair(pairb);   // partner's m reads done before epi2 overwrite

        // ---- epilogue2 IN-PLACE ----
        #pragma unroll
        for (int mi = 0; mi < 2; mi++) {
            int r0 = mrow + mi * 16 + gid;
            #pragma unroll
            for (int nj = 0; nj < 4; nj++) {
                int c0 = nbase + nj * 8 + tig * 2;
                float bb0 = b2s[c0], bb1 = b2s[c0 + 1];
                float* p00 = buf + r0 * PSTR + c0;
                float* p10 = buf + (r0 + 8) * PSTR + c0;
                p00[0] = silu(d2[mi][nj][0] + bb0);
                p00[1] = silu(d2[mi][nj][1] + bb1);
                p10[0] = silu(d2[mi][nj][2] + bb0);
                p10[1] = silu(d2[mi][nj][3] + bb1);
            }
        }
        __syncthreads();   // scatter threads read arbitrary rows + ds

        // ========== scatter: bulk add-reduce ==========
        asm volatile("fence.proxy.async.shared::cta;" ::: "memory");
        if (tid < E_TILE && base + tid < E) {
            bulk_red_add(g_hneigh + (long)ds[tid] * HH,
                         msb + tid * (PSTR * 4), HH * 4);
        }
        asm volatile("cp.async.bulk.commit_group;" ::: "memory");
    }
    asm volatile("cp.async.bulk.wait_group 0;" ::: "memory");
}

// ---------------------------------------------------------------------------
// Node kernel: tf32 mma, 1024 threads (32 warps, m16 x n32 warp tiles).
// ---------------------------------------------------------------------------
#define N_TILE 256
#define ZSTR   132
#define MSTR   68
#define NTHREADS 1024

__global__ void __launch_bounds__(NTHREADS, 1)
node_kernel(const float* __restrict__ node_feat,
            const float* __restrict__ Wn1,
            const float* __restrict__ bn1,
            const float* __restrict__ Wn2,
            const float* __restrict__ bn2,
            float* __restrict__ out,
            int N)
{
    extern __shared__ float sm[];
    float* zs  = sm;                        // 256*132 (m aliases, stride 68)
    float* W1s = zs + N_TILE * ZSTR;        // 128*72
    float* W2s = W1s + 128 * WSTR;          // 64*72
    float* b1s = W2s + HH * WSTR;
    float* b2s = b1s + HH;

    const int tid = threadIdx.x;

    for (int i = tid; i < 128 * HH; i += NTHREADS) {
        int r = i / HH, c = i % HH;
        W1s[r * WSTR + c] = __uint_as_float(f2tf(Wn1[i]));
    }
    for (int i = tid; i < HH * DD; i += NTHREADS) {
        int r = i / DD, c = i % DD;
        W2s[r * WSTR + c] = __uint_as_float(f2tf(Wn2[i]));
    }
    if (tid < HH) { b1s[tid] = bn1[tid]; b2s[tid] = bn2[tid]; }

    const int warp = tid >> 5;
    const int lane = tid & 31;
    const int gid  = lane >> 2;
    const int tig  = lane & 3;
    const int mrow  = (warp & 15) * 16;
    const int nbase = (warp >> 4) * 32;

    const float4* nf4 = (const float4*)node_feat;
    const float4* hn4 = (const float4*)g_hneigh;

    const int nTiles = (N + N_TILE - 1) / N_TILE;
    for (int t = blockIdx.x; t < nTiles; t += gridDim.x) {
        const int base = t * N_TILE;
        __syncthreads();

        for (int idx = tid; idx < N_TILE * 32; idx += NTHREADS) {
            int nl = idx >> 5, c = idx & 31;
            int n = base + nl;
            if (n >= N) n = N - 1;
            float4 v = (c < 16) ? nf4[(long)n * 16 + c]
                                : hn4[(long)n * 16 + (c - 16)];
            ((float4*)(zs + nl * ZSTR))[c] = v;
        }
        __syncthreads();

        float d1[4][4];
        #pragma unroll
        for (int nj = 0; nj < 4; nj++)
            #pragma unroll
            for (int q = 0; q < 4; q++) d1[nj][q] = 0.0f;

        const unsigned* w1u = (const unsigned*)W1s;
        #pragma unroll 4
        for (int ks = 0; ks < 16; ks++) {
            const int kk = ks * 8;
            unsigned a[4];
            {
                int r0 = mrow + gid;
                const float* fp  = zs + r0 * ZSTR + kk + tig;
                const float* fp8 = fp + 8 * ZSTR;
                a[0] = f2tf(fp[0]);
                a[1] = f2tf(fp8[0]);
                a[2] = f2tf(fp[4]);
                a[3] = f2tf(fp8[4]);
            }
            #pragma unroll
            for (int nj = 0; nj < 4; nj++) {
                int n = nbase + nj * 8 + gid;
                unsigned bb[2];
                bb[0] = w1u[(kk + tig) * WSTR + n];
                bb[1] = w1u[(kk + tig + 4) * WSTR + n];
                mma_tf32(d1[nj], a, bb);
            }
        }
        __syncthreads();

        {
            int r0 = mrow + gid;
            #pragma unroll
            for (int nj = 0; nj < 4; nj++) {
                int c0 = nbase + nj * 8 + tig * 2;
                float bb0 = b1s[c0], bb1 = b1s[c0 + 1];
                zs[r0 * MSTR + c0]
                    = __uint_as_float(f2tf(silu(d1[nj][0] + bb0)));
                zs[r0 * MSTR + c0 + 1]
                    = __uint_as_float(f2tf(silu(d1[nj][1] + bb1)));
                zs[(r0 + 8) * MSTR + c0]
                    = __uint_as_float(f2tf(silu(d1[nj][2] + bb0)));
                zs[(r0 + 8) * MSTR + c0 + 1]
                    = __uint_as_float(f2tf(silu(d1[nj][3] + bb1)));
            }
        }
        __syncthreads();

        float d2[4][4];
        #pragma unroll
        for (int nj = 0; nj < 4; nj++)
            #pragma unroll
            for (int q = 0; q < 4; q++) d2[nj][q] = 0.0f;

        const unsigned* msu = (const unsigned*)zs;
        const unsigned* w2u = (const unsigned*)W2s;
        #pragma unroll
        for (int ks = 0; ks < 8; ks++) {
            const int kk = ks * 8;
            unsigned a[4];
            {
                int r0 = mrow + gid;
                const unsigned* mp  = msu + r0 * MSTR + kk + tig;
                const unsigned* mp8 = mp + 8 * MSTR;
                a[0] = mp[0];
                a[1] = mp8[0];
                a[2] = mp[4];
                a[3] = mp8[4];
            }
            #pragma unroll
            for (int nj = 0; nj < 4; nj++) {
                int n = nbase + nj * 8 + gid;
                unsigned bb[2];
                bb[0] = w2u[(kk + tig) * WSTR + n];
                bb[1] = w2u[(kk + tig + 4) * WSTR + n];
                mma_tf32(d2[nj], a, bb);
            }
        }

        {
            int r0 = mrow + gid;
            #pragma unroll
            for (int nj = 0; nj < 4; nj++) {
                int c0 = nbase + nj * 8 + tig * 2;
                float bb0 = b2s[c0], bb1 = b2s[c0 + 1];
                int n0 = base + r0, n1 = base + r0 + 8;
                if (n0 < N)
                    *(float2*)(out + (long)n0 * DD + c0)
                        = make_float2(d2[nj][0] + bb0, d2[nj][1] + bb1);
                if (n1 < N)
                    *(float2*)(out + (long)n1 * DD + c0)
                        = make_float2(d2[nj][2] + bb0, d2[nj][3] + bb1);
            }
        }
    }
}

// ---------------------------------------------------------------------------
extern "C" void kernel_launch(void* const* d_in, const int* in_sizes, int n_in,
                              void* d_out, int out_size)
{
    const float* node_feat = (const float*)d_in[0];
    const float* coord     = (const float*)d_in[1];
    const float* edge_feat = (const float*)d_in[2];
    const int*   src       = (const int*)d_in[3];
    const int*   dst       = (const int*)d_in[4];
    const float* We1       = (const float*)d_in[5];
    const float* be1       = (const float*)d_in[6];
    const float* We2       = (const float*)d_in[7];
    const float* be2       = (const float*)d_in[8];
    const float* Wn1       = (const float*)d_in[9];
    const float* bn1       = (const float*)d_in[10];
    const float* Wn2       = (const float*)d_in[11];
    const float* bn2       = (const float*)d_in[12];
    float* out = (float*)d_out;

    const int N = in_sizes[0] / DD;
    const int E = in_sizes[3];

    const size_t smem_p =
        (size_t)(128 * ASTR + 64 * BSTR2) * sizeof(float);
    const size_t smem_edge =
        (size_t)(K1S * WSTR + HH * WSTR + 3 * HH + E_TILE + E_TILE
                 + E_TILE * PSTR + E_TILE * FSSTR)
        * sizeof(float);   // 69888 B -> 3 CTAs/SM
    const size_t smem_node =
        (size_t)(N_TILE * ZSTR + 128 * WSTR + HH * WSTR + 2 * HH)
        * sizeof(float);

    cudaFuncSetAttribute(p_kernel,
                         cudaFuncAttributeMaxDynamicSharedMemorySize,
                         (int)smem_p);
    cudaFuncSetAttribute(edge_kernel,
                         cudaFuncAttributeMaxDynamicSharedMemorySize,
                         (int)smem_edge);
    cudaFuncSetAttribute(node_kernel,
                         cudaFuncAttributeMaxDynamicSharedMemorySize,
                         (int)smem_node);

    int numSMs = 148;
    cudaDeviceGetAttribute(&numSMs, cudaDevAttrMultiProcessorCount, 0);

    // 1) P precompute + zero g_hneigh (persistent, one wave)
    int pTiles = (N + 127) / 128;
    int pGrid = 2 * numSMs;
    p_kernel<<<pGrid, 512, smem_p>>>(node_feat, We1, N, pTiles);

    // 2) edge MLP + bulk-reduce scatter (persistent, 3 CTAs/SM)
    int eTiles = (E + E_TILE - 1) / E_TILE;
    int eGrid = 3 * numSMs;
    if (eGrid > eTiles) eGrid = eTiles;
    edge_kernel<<<eGrid, ETHREADS, smem_edge>>>(
        coord, edge_feat, src, dst, We1, be1, We2, be2, E);

    // 3) node MLP
    int nTiles = (N + N_TILE - 1) / N_TILE;
    int nGrid = nTiles < numSMs ? nTiles : numSMs;
    node_kernel<<<nGrid, NTHREADS, smem_node>>>(
        node_feat, Wn1, bn1, Wn2, bn2, out, N);
}

// round 17
// speedup vs baseline: 1.0780x; 1.0780x over previous
#include <cuda_runtime.h>

// ---------------------------------------------------------------------------
// EGNN edge/node block, round 16.
// R13 config (E_TILE=128, 256 thr, 3 CTAs/SM, K1S=24 GEMM1) + R14's
// pair-local row ownership pushed to completion: each warp gathers, computes
// and bulk-scatters its own rows; ALL intra-tile ordering is 64-thread pair
// barriers (zero CTA-wide __syncthreads in the loop; the 4 pairs of a CTA
// run as independent pipelines). Persistent p_kernel, 1024-thr node kernel.
// N=50000, E=800000, D=64, H=64, EF=16.
// ---------------------------------------------------------------------------

#define NN      50000
#define DD      64
#define HH      64
#define E_TILE  128
#define WSTR    72     // weight row stride (72%32=8, conflict-free)
#define PSTR    68     // buf row stride (68%32=4); 272B row, 16B-aligned
#define FSSTR   28     // fsmall row stride (28%32=28, conflict-free)
#define K1S     24     // padded small-K of edge layer 1 (3 k-steps)

__device__ float g_hneigh[NN * HH];
__device__ float g_P[NN * 128];   // [n][0:64]=h@W1_src, [64:128]=h@W1_dst

__device__ __forceinline__ float silu(float x) {
    return x / (1.0f + __expf(-x));
}
__device__ __forceinline__ unsigned f2tf(float x) {
    unsigned r;
    asm("cvt.rna.tf32.f32 %0, %1;" : "=r"(r) : "f"(x));
    return r;
}
__device__ __forceinline__ void mma_tf32(float d[4], const unsigned a[4],
                                         const unsigned b[2]) {
    asm volatile(
        "mma.sync.aligned.m16n8k8.row.col.f32.tf32.tf32.f32 "
        "{%0,%1,%2,%3}, {%4,%5,%6,%7}, {%8,%9}, {%0,%1,%2,%3};"
        : "+f"(d[0]), "+f"(d[1]), "+f"(d[2]), "+f"(d[3])
        : "r"(a[0]), "r"(a[1]), "r"(a[2]), "r"(a[3]), "r"(b[0]), "r"(b[1]));
}
__device__ __forceinline__ void cp16(unsigned saddr, const void* g) {
    asm volatile("cp.async.ca.shared.global [%0], [%1], 16;"
                 :: "r"(saddr), "l"(g));
}
__device__ __forceinline__ void bulk_red_add(float* gptr, unsigned saddr,
                                             int bytes) {
    unsigned long long g;
    asm("cvta.to.global.u64 %0, %1;" : "=l"(g) : "l"(gptr));
    asm volatile(
        "cp.reduce.async.bulk.global.shared::cta.bulk_group.add.f32 "
        "[%0], [%1], %2;"
        :: "l"(g), "r"(saddr), "r"(bytes) : "memory");
}
__device__ __forceinline__ void bar_pair(int id) {
    asm volatile("bar.sync %0, 64;" :: "r"(id) : "memory");
}

// ---------------------------------------------------------------------------
// P kernel: persistent single wave (2 CTAs/SM). P tiles + fused zeroing.
// ---------------------------------------------------------------------------
#define ASTR  68
#define BSTR2 136

__global__ void __launch_bounds__(512, 2)
p_kernel(const float* __restrict__ node_feat,
         const float* __restrict__ We1,
         int N, int pTiles)
{
    const int tid = threadIdx.x;

    extern __shared__ float sm[];
    float* As = sm;                 // 128*68
    float* Bs = As + 128 * ASTR;    // 64*136

    for (int i = tid; i < 64 * 128; i += 512) {
        int k = i >> 7, j = i & 127;
        float v = (j < 64) ? We1[k * HH + j] : We1[(64 + k) * HH + (j - 64)];
        Bs[k * BSTR2 + j] = __uint_as_float(f2tf(v));
    }

    const int warp = tid >> 5, lane = tid & 31;
    const int gid = lane >> 2, tig = lane & 3;
    const int mrow  = (warp & 3) * 32;
    const int nbase = (warp >> 2) * 32;
    const float4* nf4 = (const float4*)node_feat;
    const unsigned* bu = (const unsigned*)Bs;

    for (int t = blockIdx.x; t < pTiles; t += gridDim.x) {
        const int base = t * 128;
        __syncthreads();

        for (int idx = tid; idx < 128 * 16; idx += 512) {
            int r = idx >> 4, c = idx & 15;
            int n = base + r;
            if (n >= N) n = N - 1;
            ((float4*)(As + r * ASTR))[c] = nf4[(long)n * 16 + c];
        }
        __syncthreads();

        float d[2][4][4];
        #pragma unroll
        for (int mi = 0; mi < 2; mi++)
            #pragma unroll
            for (int nj = 0; nj < 4; nj++)
                #pragma unroll
                for (int q = 0; q < 4; q++) d[mi][nj][q] = 0.0f;

        #pragma unroll
        for (int ks = 0; ks < 8; ks++) {
            const int kk = ks * 8;
            unsigned a[2][4];
            #pragma unroll
            for (int mi = 0; mi < 2; mi++) {
                int r0 = mrow + mi * 16 + gid;
                const float* fp  = As + r0 * ASTR + kk + tig;
                const float* fp8 = fp + 8 * ASTR;
                a[mi][0] = f2tf(fp[0]);
                a[mi][1] = f2tf(fp8[0]);
                a[mi][2] = f2tf(fp[4]);
                a[mi][3] = f2tf(fp8[4]);
            }
            #pragma unroll
            for (int nj = 0; nj < 4; nj++) {
                int n = nbase + nj * 8 + gid;
                unsigned bb[2];
                bb[0] = bu[(kk + tig) * BSTR2 + n];
                bb[1] = bu[(kk + tig + 4) * BSTR2 + n];
                mma_tf32(d[0][nj], a[0], bb);
                mma_tf32(d[1][nj], a[1], bb);
            }
        }
        #pragma unroll
        for (int mi = 0; mi < 2; mi++) {
            int r0 = mrow + mi * 16 + gid;
            #pragma unroll
            for (int nj = 0; nj < 4; nj++) {
                int c0 = nbase + nj * 8 + tig * 2;
                int n0 = base + r0, n1 = base + r0 + 8;
                if (n0 < N)
                    *(float2*)(g_P + (long)n0 * 128 + c0)
                        = make_float2(d[mi][nj][0], d[mi][nj][1]);
                if (n1 < N)
                    *(float2*)(g_P + (long)n1 * 128 + c0)
                        = make_float2(d[mi][nj][2], d[mi][nj][3]);
            }
        }
    }

    {
        float4* h4 = (float4*)g_hneigh;
        const int total4 = NN * HH / 4;
        for (int i = blockIdx.x * 512 + tid; i < total4; i += gridDim.x * 512)
            h4[i] = make_float4(0.f, 0.f, 0.f, 0.f);
    }
}

// ---------------------------------------------------------------------------
// Edge kernel. Pair-decoupled: warp w owns rows grow..grow+15
// (grow = (w&3)*32 + (w>>2)*16) for gather, ds, radial, and bulk scatter.
// All ordering via 64-thread pair barriers; no CTA syncs in the loop.
// ---------------------------------------------------------------------------
#define ETHREADS 256

__global__ void __launch_bounds__(ETHREADS, 3)
edge_kernel(const float* __restrict__ coord,
            const float* __restrict__ edge_feat,
            const int*   __restrict__ src,
            const int*   __restrict__ dst,
            const float* __restrict__ We1,
            const float* __restrict__ be1,
            const float* __restrict__ We2,
            const float* __restrict__ be2,
            int E)
{
    extern __shared__ float sm[];
    float* W1s    = sm;                      // 24*72
    float* W2s    = W1s + K1S * WSTR;        // 64*72
    float* b1s    = W2s + HH * WSTR;         // 64
    float* b2s    = b1s + HH;                // 64
    int*   ds     = (int*)(b2s + HH);        // 128
    float* buf    = (float*)(ds + E_TILE);   // 128*68 (presum/m/msg)
    float* fsmall = buf + E_TILE * PSTR;     // 128*28
    // total 75520 B -> 3 CTAs/SM

    const int tid = threadIdx.x;

    for (int i = tid; i < K1S * HH; i += ETHREADS) {
        int r = i / HH, c = i % HH;
        float v = 0.0f;
        if (r < 16)       v = We1[(129 + r) * HH + c];
        else if (r == 16) v = We1[128 * HH + c];
        W1s[r * WSTR + c] = __uint_as_float(f2tf(v));
    }
    for (int i = tid; i < HH * HH; i += ETHREADS) {
        int r = i / HH, c = i % HH;
        W2s[r * WSTR + c] = __uint_as_float(f2tf(We2[i]));
    }
    if (tid < HH) { b1s[tid] = be1[tid]; b2s[tid] = be2[tid]; }
    for (int i = tid; i < E_TILE * 11; i += ETHREADS) {
        int r = i / 11, c = 17 + (i % 11);
        fsmall[r * FSSTR + c] = 0.0f;
    }

    const int warp = tid >> 5;
    const int lane = tid & 31;
    const int gid  = lane >> 2;
    const int tig  = lane & 3;
    const int mrow  = (warp & 3) * 32;
    const int nbase = (warp >> 2) * 32;
    const int pairb = 1 + (warp & 3);        // named barrier id per row-group
    const int grow  = (warp & 3) * 32 + (warp >> 2) * 16;  // owned rows
    const int half  = lane >> 4;             // 0/1
    const int j     = lane & 15;             // 0..15

    const float4* P4 = (const float4*)g_P;
    const unsigned fsb = (unsigned)__cvta_generic_to_shared(fsmall);
    const unsigned msb = (unsigned)__cvta_generic_to_shared(buf);

    __syncthreads();   // weights + pad ready (only CTA sync)

    const int nTiles = (E + E_TILE - 1) / E_TILE;
    for (int t = blockIdx.x; t < nTiles; t += gridDim.x) {
        const int base = t * E_TILE;

        // ========== STAGE A (own rows only; no buf/ds writes) ==========
        const int eb = base + grow;
        int egi = eb + j; if (egi >= E) egi = E - 1;
        const int myidx = (lane < 16) ? src[egi] : dst[egi];

        #pragma unroll
        for (int r = 0; r < 2; r++) {
            int el = grow + r * 8 + (lane >> 2);
            int eg = base + el; if (eg >= E) eg = E - 1;
            int c = lane & 3;
            cp16(fsb + el * (FSSTR * 4) + c * 16,
                 edge_feat + (long)eg * 16 + c * 4);
        }
        asm volatile("cp.async.commit_group;");

        int s_r = __shfl_sync(0xffffffffu, myidx, j);
        int d_r = __shfl_sync(0xffffffffu, myidx, 16 + j);
        if (lane < 16) {
            float cx = coord[s_r * 3 + 0] - coord[d_r * 3 + 0];
            float cy = coord[s_r * 3 + 1] - coord[d_r * 3 + 1];
            float cz = coord[s_r * 3 + 2] - coord[d_r * 3 + 2];
            fsmall[(grow + j) * FSSTR + 16]
                = cx * cx + cy * cy + cz * cz;
        }

        // chunk-1 P gather BEFORE bulk drain (overlaps the wait)
        float4 ps1[4], pd1[4];
        #pragma unroll
        for (int i = 0; i < 4; i++) {
            int el = i * 2 + half;
            int s = __shfl_sync(0xffffffffu, myidx, el);
            int d = __shfl_sync(0xffffffffu, myidx, 16 + el);
            ps1[i] = P4[(long)s * 32 + j];
            pd1[i] = P4[(long)d * 32 + 16 + j];
        }

        // ===== warp-local drain: this warp's own bulk ops covered exactly
        //       the rows grow..grow+15 it is about to overwrite =====
        asm volatile("cp.async.bulk.wait_group 0;" ::: "memory");

        // presum store (own rows)
        #pragma unroll
        for (int i = 0; i < 4; i++) {
            int el = grow + i * 2 + half;
            float4 v = make_float4(ps1[i].x + pd1[i].x, ps1[i].y + pd1[i].y,
                                   ps1[i].z + pd1[i].z, ps1[i].w + pd1[i].w);
            *(float4*)(buf + el * PSTR + j * 4) = v;
        }
        {
            float4 ps2[4], pd2[4];
            #pragma unroll
            for (int i = 0; i < 4; i++) {
                int el = (4 + i) * 2 + half;
                int s = __shfl_sync(0xffffffffu, myidx, el);
                int d = __shfl_sync(0xffffffffu, myidx, 16 + el);
                ps2[i] = P4[(long)s * 32 + j];
                pd2[i] = P4[(long)d * 32 + 16 + j];
            }
            #pragma unroll
            for (int i = 0; i < 4; i++) {
                int el = grow + (4 + i) * 2 + half;
                float4 v = make_float4(ps2[i].x + pd2[i].x, ps2[i].y + pd2[i].y,
                                       ps2[i].z + pd2[i].z, ps2[i].w + pd2[i].w);
                *(float4*)(buf + el * PSTR + j * 4) = v;
            }
        }
        if (lane >= 16) ds[grow + j] = d_r;

        asm volatile("cp.async.wait_group 0;");
        // partner's half of the 32-row group ready
        bar_pair(pairb);

        // ========== GEMM1: [128,24]@[24,64] (own 32 rows) ==========
        float d1[2][4][4];
        #pragma unroll
        for (int mi = 0; mi < 2; mi++)
            #pragma unroll
            for (int nj = 0; nj < 4; nj++)
                #pragma unroll
                for (int q = 0; q < 4; q++) d1[mi][nj][q] = 0.0f;

        const unsigned* w1u = (const unsigned*)W1s;
        #pragma unroll
        for (int ks = 0; ks < 3; ks++) {
            const int kk = ks * 8;
            unsigned a[2][4];
            #pragma unroll
            for (int mi = 0; mi < 2; mi++) {
                int r0 = mrow + mi * 16 + gid;
                const float* fp  = fsmall + r0 * FSSTR + kk + tig;
                const float* fp8 = fp + 8 * FSSTR;
                a[mi][0] = f2tf(fp[0]);
                a[mi][1] = f2tf(fp8[0]);
                a[mi][2] = f2tf(fp[4]);
                a[mi][3] = f2tf(fp8[4]);
            }
            #pragma unroll
            for (int nj = 0; nj < 4; nj++) {
                int n = nbase + nj * 8 + gid;
                unsigned bb[2];
                bb[0] = w1u[(kk + tig) * WSTR + n];
                bb[1] = w1u[(kk + tig + 4) * WSTR + n];
                mma_tf32(d1[0][nj], a[0], bb);
                mma_tf32(d1[1][nj], a[1], bb);
            }
        }

        // ---- epilogue1 IN-PLACE (own rows/cols) ----
        #pragma unroll
        for (int mi = 0; mi < 2; mi++) {
            int r0 = mrow + mi * 16 + gid;
            #pragma unroll
            for (int nj = 0; nj < 4; nj++) {
                int c0 = nbase + nj * 8 + tig * 2;
                float bb0 = b1s[c0], bb1 = b1s[c0 + 1];
                float* p00 = buf + r0 * PSTR + c0;
                float* p10 = buf + (r0 + 8) * PSTR + c0;
                p00[0] = __uint_as_float(f2tf(silu(d1[mi][nj][0] + p00[0] + bb0)));
                p00[1] = __uint_as_float(f2tf(silu(d1[mi][nj][1] + p00[1] + bb1)));
                p10[0] = __uint_as_float(f2tf(silu(d1[mi][nj][2] + p10[0] + bb0)));
                p10[1] = __uint_as_float(f2tf(silu(d1[mi][nj][3] + p10[1] + bb1)));
            }
        }
        bar_pair(pairb);   // partner must see m complete

        // ========== GEMM2: [128,64]@[64,64] (own rows, all cols) ==========
        float d2[2][4][4];
        #pragma unroll
        for (int mi = 0; mi < 2; mi++)
            #pragma unroll
            for (int nj = 0; nj < 4; nj++)
                #pragma unroll
                for (int q = 0; q < 4; q++) d2[mi][nj][q] = 0.0f;

        const unsigned* msu = (const unsigned*)buf;
        const unsigned* w2u = (const unsigned*)W2s;
        #pragma unroll
        for (int ks = 0; ks < 8; ks++) {
            const int kk = ks * 8;
            unsigned a[2][4];
            #pragma unroll
            for (int mi = 0; mi < 2; mi++) {
                int r0 = mrow + mi * 16 + gid;
                const unsigned* mp  = msu + r0 * PSTR + kk + tig;
                const unsigned* mp8 = mp + 8 * PSTR;
                a[mi][0] = mp[0];
                a[mi][1] = mp8[0];
                a[mi][2] = mp[4];
                a[mi][3] = mp8[4];
            }
            #pragma unroll
            for (int nj = 0; nj < 4; nj++) {
                int n = nbase + nj * 8 + gid;
                unsigned bb[2];
                bb[0] = w2u[(kk + tig) * WSTR + n];
                bb[1] = w2u[(kk + tig + 4) * WSTR + n];
                mma_tf32(d2[0][nj], a[0], bb);
                mma_tf32(d2[1][nj], a[1], bb);
            }
        }
        bar_pair(pairb);   // partner's m reads done before epi2 overwrite

        // ---- epilogue2 IN-PLACE ----
        #pragma unroll
        for (int mi = 0; mi < 2; mi++) {
            int r0 = mrow + mi * 16 + gid;
            #pragma unroll
            for (int nj = 0; nj < 4; nj++) {
                int c0 = nbase + nj * 8 + tig * 2;
                float bb0 = b2s[c0], bb1 = b2s[c0 + 1];
                float* p00 = buf + r0 * PSTR + c0;
                float* p10 = buf + (r0 + 8) * PSTR + c0;
                p00[0] = silu(d2[mi][nj][0] + bb0);
                p00[1] = silu(d2[mi][nj][1] + bb1);
                p10[0] = silu(d2[mi][nj][2] + bb0);
                p10[1] = silu(d2[mi][nj][3] + bb1);
            }
        }
        bar_pair(pairb);   // pair's msg rows complete before scatter

        // ========== scatter: each warp bulk-reduces its own 16 rows ======
        asm volatile("fence.proxy.async.shared::cta;" ::: "memory");
        if (lane < 16) {
            int r = grow + lane;
            if (base + r < E) {
                bulk_red_add(g_hneigh + (long)ds[r] * HH,
                             msb + r * (PSTR * 4), HH * 4);
            }
        }
        asm volatile("cp.async.bulk.commit_group;" ::: "memory");
    }
    asm volatile("cp.async.bulk.wait_group 0;" ::: "memory");
}

// ---------------------------------------------------------------------------
// Node kernel: tf32 mma, 1024 threads (32 warps, m16 x n32 warp tiles).
// ---------------------------------------------------------------------------
#define N_TILE 256
#define ZSTR   132
#define MSTR   68
#define NTHREADS 1024

__global__ void __launch_bounds__(NTHREADS, 1)
node_kernel(const float* __restrict__ node_feat,
            const float* __restrict__ Wn1,
            const float* __restrict__ bn1,
            const float* __restrict__ Wn2,
            const float* __restrict__ bn2,
            float* __restrict__ out,
            int N)
{
    extern __shared__ float sm[];
    float* zs  = sm;                        // 256*132 (m aliases, stride 68)
    float* W1s = zs + N_TILE * ZSTR;        // 128*72
    float* W2s = W1s + 128 * WSTR;          // 64*72
    float* b1s = W2s + HH * WSTR;
    float* b2s = b1s + HH;

    const int tid = threadIdx.x;

    for (int i = tid; i < 128 * HH; i += NTHREADS) {
        int r = i / HH, c = i % HH;
        W1s[r * WSTR + c] = __uint_as_float(f2tf(Wn1[i]));
    }
    for (int i = tid; i < HH * DD; i += NTHREADS) {
        int r = i / DD, c = i % DD;
        W2s[r * WSTR + c] = __uint_as_float(f2tf(Wn2[i]));
    }
    if (tid < HH) { b1s[tid] = bn1[tid]; b2s[tid] = bn2[tid]; }

    const int warp = tid >> 5;
    const int lane = tid & 31;
    const int gid  = lane >> 2;
    const int tig  = lane & 3;
    const int mrow  = (warp & 15) * 16;
    const int nbase = (warp >> 4) * 32;

    const float4* nf4 = (const float4*)node_feat;
    const float4* hn4 = (const float4*)g_hneigh;

    const int nTiles = (N + N_TILE - 1) / N_TILE;
    for (int t = blockIdx.x; t < nTiles; t += gridDim.x) {
        const int base = t * N_TILE;
        __syncthreads();

        for (int idx = tid; idx < N_TILE * 32; idx += NTHREADS) {
            int nl = idx >> 5, c = idx & 31;
            int n = base + nl;
            if (n >= N) n = N - 1;
            float4 v = (c < 16) ? nf4[(long)n * 16 + c]
                                : hn4[(long)n * 16 + (c - 16)];
            ((float4*)(zs + nl * ZSTR))[c] = v;
        }
        __syncthreads();

        float d1[4][4];
        #pragma unroll
        for (int nj = 0; nj < 4; nj++)
            #pragma unroll
            for (int q = 0; q < 4; q++) d1[nj][q] = 0.0f;

        const unsigned* w1u = (const unsigned*)W1s;
        #pragma unroll 4
        for (int ks = 0; ks < 16; ks++) {
            const int kk = ks * 8;
            unsigned a[4];
            {
                int r0 = mrow + gid;
                const float* fp  = zs + r0 * ZSTR + kk + tig;
                const float* fp8 = fp + 8 * ZSTR;
                a[0] = f2tf(fp[0]);
                a[1] = f2tf(fp8[0]);
                a[2] = f2tf(fp[4]);
                a[3] = f2tf(fp8[4]);
            }
            #pragma unroll
            for (int nj = 0; nj < 4; nj++) {
                int n = nbase + nj * 8 + gid;
                unsigned bb[2];
                bb[0] = w1u[(kk + tig) * WSTR + n];
                bb[1] = w1u[(kk + tig + 4) * WSTR + n];
                mma_tf32(d1[nj], a, bb);
            }
        }
        __syncthreads();

        {
            int r0 = mrow + gid;
            #pragma unroll
            for (int nj = 0; nj < 4; nj++) {
                int c0 = nbase + nj * 8 + tig * 2;
                float bb0 = b1s[c0], bb1 = b1s[c0 + 1];
                zs[r0 * MSTR + c0]
                    = __uint_as_float(f2tf(silu(d1[nj][0] + bb0)));
                zs[r0 * MSTR + c0 + 1]
                    = __uint_as_float(f2tf(silu(d1[nj][1] + bb1)));
                zs[(r0 + 8) * MSTR + c0]
                    = __uint_as_float(f2tf(silu(d1[nj][2] + bb0)));
                zs[(r0 + 8) * MSTR + c0 + 1]
                    = __uint_as_float(f2tf(silu(d1[nj][3] + bb1)));
            }
        }
        __syncthreads();

        float d2[4][4];
        #pragma unroll
        for (int nj = 0; nj < 4; nj++)
            #pragma unroll
            for (int q = 0; q < 4; q++) d2[nj][q] = 0.0f;

        const unsigned* msu = (const unsigned*)zs;
        const unsigned* w2u = (const unsigned*)W2s;
        #pragma unroll
        for (int ks = 0; ks < 8; ks++) {
            const int kk = ks * 8;
            unsigned a[4];
            {
                int r0 = mrow + gid;
                const unsigned* mp  = msu + r0 * MSTR + kk + tig;
                const unsigned* mp8 = mp + 8 * MSTR;
                a[0] = mp[0];
                a[1] = mp8[0];
                a[2] = mp[4];
                a[3] = mp8[4];
            }
            #pragma unroll
            for (int nj = 0; nj < 4; nj++) {
                int n = nbase + nj * 8 + gid;
                unsigned bb[2];
                bb[0] = w2u[(kk + tig) * WSTR + n];
                bb[1] = w2u[(kk + tig + 4) * WSTR + n];
                mma_tf32(d2[nj], a, bb);
            }
        }

        {
            int r0 = mrow + gid;
            #pragma unroll
            for (int nj = 0; nj < 4; nj++) {
                int c0 = nbase + nj * 8 + tig * 2;
                float bb0 = b2s[c0], bb1 = b2s[c0 + 1];
                int n0 = base + r0, n1 = base + r0 + 8;
                if (n0 < N)
                    *(float2*)(out + (long)n0 * DD + c0)
                        = make_float2(d2[nj][0] + bb0, d2[nj][1] + bb1);
                if (n1 < N)
                    *(float2*)(out + (long)n1 * DD + c0)
                        = make_float2(d2[nj][2] + bb0, d2[nj][3] + bb1);
            }
        }
    }
}

// ---------------------------------------------------------------------------
extern "C" void kernel_launch(void* const* d_in, const int* in_sizes, int n_in,
                              void* d_out, int out_size)
{
    const float* node_feat = (const float*)d_in[0];
    const float* coord     = (const float*)d_in[1];
    const float* edge_feat = (const float*)d_in[2];
    const int*   src       = (const int*)d_in[3];
    const int*   dst       = (const int*)d_in[4];
    const float* We1       = (const float*)d_in[5];
    const float* be1       = (const float*)d_in[6];
    const float* We2       = (const float*)d_in[7];
    const float* be2       = (const float*)d_in[8];
    const float* Wn1       = (const float*)d_in[9];
    const float* bn1       = (const float*)d_in[10];
    const float* Wn2       = (const float*)d_in[11];
    const float* bn2       = (const float*)d_in[12];
    float* out = (float*)d_out;

    const int N = in_sizes[0] / DD;
    const int E = in_sizes[3];

    const size_t smem_p =
        (size_t)(128 * ASTR + 64 * BSTR2) * sizeof(float);
    const size_t smem_edge =
        (size_t)(K1S * WSTR + HH * WSTR + 2 * HH + E_TILE
                 + E_TILE * PSTR + E_TILE * FSSTR)
        * sizeof(float);   // 75520 B -> 3 CTAs/SM
    const size_t smem_node =
        (size_t)(N_TILE * ZSTR + 128 * WSTR + HH * WSTR + 2 * HH)
        * sizeof(float);

    cudaFuncSetAttribute(p_kernel,
                         cudaFuncAttributeMaxDynamicSharedMemorySize,
                         (int)smem_p);
    cudaFuncSetAttribute(edge_kernel,
                         cudaFuncAttributeMaxDynamicSharedMemorySize,
                         (int)smem_edge);
    cudaFuncSetAttribute(node_kernel,
                         cudaFuncAttributeMaxDynamicSharedMemorySize,
                         (int)smem_node);

    int numSMs = 148;
    cudaDeviceGetAttribute(&numSMs, cudaDevAttrMultiProcessorCount, 0);

    // 1) P precompute + zero g_hneigh (persistent, one wave)
    int pTiles = (N + 127) / 128;
    int pGrid = 2 * numSMs;
    p_kernel<<<pGrid, 512, smem_p>>>(node_feat, We1, N, pTiles);

    // 2) edge MLP + bulk-reduce scatter (persistent, 3 CTAs/SM)
    int eTiles = (E + E_TILE - 1) / E_TILE;
    int eGrid = 3 * numSMs;
    if (eGrid > eTiles) eGrid = eTiles;
    edge_kernel<<<eGrid, ETHREADS, smem_edge>>>(
        coord, edge_feat, src, dst, We1, be1, We2, be2, E);

    // 3) node MLP
    int nTiles = (N + N_TILE - 1) / N_TILE;
    int nGrid = nTiles < numSMs ? nTiles : numSMs;
    node_kernel<<<nGrid, NTHREADS, smem_node>>>(
        node_feat, Wn1, bn1, Wn2, bn2, out, N);
}